// round 16
// baseline (speedup 1.0000x reference)
#include <cuda_runtime.h>
#include <cuda_bf16.h>
#include <math.h>

// BERTEmbedding: out[row, 0:256]   = x[row,0:10] @ W[256,10]^T + b
//                out[row, 256:512] = sinusoidal PE at pos = doy[row]
// rows = B*S = 131072; output 268 MB fp32 -> HBM-write-bound.
//
// R16 = R11/R15 coupled-tile skeleton with R=16 (half the barriers, double the
// store burst per phase). Evidence R7-R15: DRAM parks at 50-60% while occ /
// issue / pipe mix vary wildly -> store-path ceiling ~4.5-4.8 TB/s; the lever
// left is fewer sync quanta + deeper uninterrupted store bursts.
//  - obs warps 0-3: 2 cols/thread, W in 20 regs, x via double-buffered smem
//    (float2 staging LDGs, float2 LDS reads), imm-offset STG.64.
//  - PE warps 4-7: one MUFU __sincosf pair/row from staged doy, imm-offset STG.64.

#define TPB   256
#define R     16
#define NBLK  888   // 148 SMs * 6 resident blocks; grid-stride over tiles

__global__ void __launch_bounds__(TPB, 6) bert_embed_kernel(
    const float* __restrict__ x,      // [rows, 10]
    const int*   __restrict__ doy,    // [rows]
    const float* __restrict__ W,      // [256, 10] row-major
    const float* __restrict__ bias,   // [256]
    float*       __restrict__ out,    // [rows, 512]
    int nrows)
{
    __shared__ float2 s_x2[2][R * 5];     // staged x tile (80 float2/buf)
    __shared__ int    s_doy[2][R];

    const int  t      = threadIdx.x;
    const bool is_obs = (t < 128);

    // ---- loop-invariant per-thread constants ----
    float2 wv[10];
    float2 bv  = make_float2(0.f, 0.f);
    float  div = 0.f;
    if (is_obs) {
        const int c0 = t * 2;                          // output cols 2t, 2t+1
        #pragma unroll
        for (int f = 0; f < 10; ++f)
            wv[f] = make_float2(W[c0 * 10 + f], W[(c0 + 1) * 10 + f]);
        bv = make_float2(bias[c0], bias[c0 + 1]);
    } else {
        const int   i = t - 128;
        const float k = -9.210340371976184f / 256.0f;  // -ln(10000)/D
        div = expf(k * (float)(2 * i));
    }

    float2*       o2 = reinterpret_cast<float2*>(out);        // [rows][256]
    const float2* x2 = reinterpret_cast<const float2*>(x);    // [rows*5]

    const int ntiles = (nrows + R - 1) / R;
    const int nx2    = nrows * 5;

    // stage first tile: threads 0..79 -> x (80 float2), 96..111 -> doy
    int tile = blockIdx.x;
    {
        const int base = tile * R;
        if (t < R * 5) {
            const int gi = base * 5 + t;
            s_x2[0][t] = (gi < nx2) ? __ldg(x2 + gi) : make_float2(0.f, 0.f);
        } else if (t >= 96 && t < 96 + R) {
            const int r = t - 96;
            s_doy[0][r] = (base + r < nrows) ? doy[base + r] : 0;
        }
    }
    __syncthreads();

    // per-tile output base pointer; unrolled row offsets become immediates
    float2*      op    = o2 + (size_t)tile * R * 256 + t;  // obs: col-pair t; PE: 128+(t-128)
    const size_t tstep = (size_t)gridDim.x * R * 256;

    int buf = 0;
    for (; tile < ntiles; tile += gridDim.x, buf ^= 1, op += tstep) {
        // prefetch next tile into the other buffer
        const int ntile = tile + gridDim.x;
        if (ntile < ntiles) {
            const int nb = ntile * R;
            if (t < R * 5) {
                const int gi = nb * 5 + t;
                s_x2[buf ^ 1][t] = (gi < nx2) ? __ldg(x2 + gi)
                                              : make_float2(0.f, 0.f);
            } else if (t >= 96 && t < 96 + R) {
                const int r = t - 96;
                s_doy[buf ^ 1][r] = (nb + r < nrows) ? doy[nb + r] : 0;
            }
        }

        const int rowbase = tile * R;
        if (is_obs) {
            #pragma unroll
            for (int r = 0; r < R; ++r) {
                if (rowbase + r >= nrows) break;
                float2 acc = bv;
                #pragma unroll
                for (int k2 = 0; k2 < 5; ++k2) {
                    const float2 p = s_x2[buf][r * 5 + k2];   // LDS.64 bcast
                    acc.x = fmaf(p.x, wv[2 * k2].x, acc.x);
                    acc.y = fmaf(p.x, wv[2 * k2].y, acc.y);
                    acc.x = fmaf(p.y, wv[2 * k2 + 1].x, acc.x);
                    acc.y = fmaf(p.y, wv[2 * k2 + 1].y, acc.y);
                }
                op[r * 256] = acc;                     // imm offset (r*2KB)
            }
        } else {
            #pragma unroll
            for (int r = 0; r < R; ++r) {
                if (rowbase + r >= nrows) break;
                const float pos = (float)s_doy[buf][r];
                float2 v;
                __sincosf(pos * div, &v.x, &v.y);      // RRO + MUFU pair
                op[r * 256] = v;                       // imm offset
            }
        }
        __syncthreads();
    }
}

extern "C" void kernel_launch(void* const* d_in, const int* in_sizes, int n_in,
                              void* d_out, int out_size) {
    const float* x    = (const float*)d_in[0];   // input_sequence [B,S,10]
    const int*   doy  = (const int*)  d_in[1];   // doy_sequence   [B,S]
    const float* W    = (const float*)d_in[2];   // W [256,10]
    const float* bias = (const float*)d_in[3];   // b [256]
    float*       out  = (float*)d_out;           // [B,S,512]

    const int nrows = in_sizes[1];               // B*S

    bert_embed_kernel<<<NBLK, TPB>>>(x, doy, W, bias, out, nrows);
}

// round 17
// speedup vs baseline: 1.0956x; 1.0956x over previous
#include <cuda_runtime.h>
#include <cuda_bf16.h>
#include <math.h>

// BERTEmbedding: out[row, 0:256]   = x[row,0:10] @ W[256,10]^T + b
//                out[row, 256:512] = sinusoidal PE at pos = doy[row]
// rows = B*S = 131072; output 268 MB fp32 -> HBM-write-bound.
//
// R17 = EXACT R11 kernel (best measured: 44.9us main / 48.35 total; R12-R16
// restructures all regressed or were flat) + ONE change: output stores use
// st.global.cs (__stcs, evict-first). Output is write-once/never-read; 268MB
// streaming through the 126MB L2 under evict-normal forces bursty capacity-
// eviction writebacks. Streaming hint -> eager, ordered writeback scheduling.

#define TPB   256
#define R     8
#define NBLK  888   // 148 SMs * 6 resident blocks; grid-stride over tiles

__global__ void __launch_bounds__(TPB, 6) bert_embed_kernel(
    const float* __restrict__ x,      // [rows, 10]
    const int*   __restrict__ doy,    // [rows]
    const float* __restrict__ W,      // [256, 10] row-major
    const float* __restrict__ bias,   // [256]
    float*       __restrict__ out,    // [rows, 512]
    int nrows)
{
    __shared__ float s_x[2][R * 10];      // staged x tile (80 floats/buf)
    __shared__ int   s_doy[2][R];

    const int  t      = threadIdx.x;
    const bool is_obs = (t < 128);

    // ---- loop-invariant per-thread constants ----
    // obs thread t: output cols 2t, 2t+1 -> 10x float2 of W + bias float2.
    // PE thread (t-128)=i: cols 256+2i (sin), 257+2i (cos); freq div(i).
    float2 wv[10];
    float2 bv  = make_float2(0.f, 0.f);
    float  div = 0.f;
    if (is_obs) {
        const int c0 = t * 2;
        #pragma unroll
        for (int f = 0; f < 10; ++f)
            wv[f] = make_float2(W[c0 * 10 + f], W[(c0 + 1) * 10 + f]);
        bv = make_float2(bias[c0], bias[c0 + 1]);
    } else {
        const int   i = t - 128;
        const float k = -9.210340371976184f / 256.0f;  // -ln(10000)/D
        div = expf(k * (float)(2 * i));
    }

    float2* o2 = reinterpret_cast<float2*>(out);       // [rows][256]

    const int ntiles = (nrows + R - 1) / R;

    // stage first tile
    int tile = blockIdx.x;
    {
        const int base = tile * R;
        if (t < R * 10) {
            const int gi = base * 10 + t;
            s_x[0][t] = (gi < nrows * 10) ? x[gi] : 0.f;
        } else if (t >= 96 && t < 96 + R) {
            const int r = t - 96;
            s_doy[0][r] = (base + r < nrows) ? doy[base + r] : 0;
        }
    }
    __syncthreads();

    int buf = 0;
    for (; tile < ntiles; tile += gridDim.x, buf ^= 1) {
        // prefetch next tile into the other buffer
        const int ntile = tile + gridDim.x;
        if (ntile < ntiles) {
            const int nb = ntile * R;
            if (t < R * 10) {
                const int gi = nb * 10 + t;
                s_x[buf ^ 1][t] = (gi < nrows * 10) ? x[gi] : 0.f;
            } else if (t >= 96 && t < 96 + R) {
                const int r = t - 96;
                s_doy[buf ^ 1][r] = (nb + r < nrows) ? doy[nb + r] : 0;
            }
        }

        const int rowbase = tile * R;
        if (is_obs) {
            #pragma unroll
            for (int r = 0; r < R; ++r) {
                const int row = rowbase + r;
                if (row >= nrows) break;
                float2 acc = bv;
                #pragma unroll
                for (int f = 0; f < 10; ++f) {
                    const float xv = s_x[buf][r * 10 + f];   // broadcast LDS
                    acc.x = fmaf(xv, wv[f].x, acc.x);
                    acc.y = fmaf(xv, wv[f].y, acc.y);
                }
                __stcs(&o2[(size_t)row * 256 + t], acc);    // streaming store
            }
        } else {
            const int i = t - 128;
            #pragma unroll
            for (int r = 0; r < R; ++r) {
                const int row = rowbase + r;
                if (row >= nrows) break;
                const float pos = (float)s_doy[buf][r];
                float2 v;
                __sincosf(pos * div, &v.x, &v.y);           // MUFU pair
                __stcs(&o2[(size_t)row * 256 + 128 + i], v); // streaming store
            }
        }
        __syncthreads();
    }
}

extern "C" void kernel_launch(void* const* d_in, const int* in_sizes, int n_in,
                              void* d_out, int out_size) {
    const float* x    = (const float*)d_in[0];   // input_sequence [B,S,10]
    const int*   doy  = (const int*)  d_in[1];   // doy_sequence   [B,S]
    const float* W    = (const float*)d_in[2];   // W [256,10]
    const float* bias = (const float*)d_in[3];   // b [256]
    float*       out  = (float*)d_out;           // [B,S,512]

    const int nrows = in_sizes[1];               // B*S

    bert_embed_kernel<<<NBLK, TPB>>>(x, doy, W, bias, out, nrows);
}